// round 15
// baseline (speedup 1.0000x reference)
#include <cuda_runtime.h>
#include <cuda_bf16.h>
#include <math.h>
#include <stdint.h>

// ---------------- problem constants ----------------
#define B_   1024
#define U_   1024
#define I_   64
#define TMAX 256
#define KSEG 1088              // 64 (x) + 1024 (h)
#define NSTG 51                // 3 segments * 17 stages
#define STG_PER_SEG 17

// ---------------- GEMM tiling ----------------
#define MT   64                // batch rows per CTA
#define NT   128               // gate-cols per CTA (32 units * 4 gates)
#define KC   64                // K per smem stage (64 bf16 = 128B = SW128 row)
#define NTHR 256               // 8 warps, warp tile 32x32 (2m x 4n)

#define STAGE_BYTES 24576      // A 8KB + B 16KB
#define S_A_OFF     1024
#define S_TOTAL     (S_A_OFF + 2 * STAGE_BYTES)   // 50176 -> 4 CTAs/SM

// ---------------- device scratch (static, allocation-free) ----------------
__device__ __align__(256) __nv_bfloat16 g_Whi[4096 * KSEG];
__device__ __align__(256) __nv_bfloat16 g_Wlo[4096 * KSEG];
__device__ __align__(256) __nv_bfloat16 g_Xhi[B_ * TMAX * I_];
__device__ __align__(256) __nv_bfloat16 g_Xlo[B_ * TMAX * I_];
__device__ __align__(256) __nv_bfloat16 g_Ahh[2][B_ * U_];
__device__ __align__(256) __nv_bfloat16 g_Ahl[2][B_ * U_];
__device__ __align__(256) __nv_bfloat16 g_ph[B_ * I_];
__device__ __align__(256) __nv_bfloat16 g_pl[B_ * I_];
__device__ float g_c[B_ * U_];
__device__ float g_h[B_ * U_];

__device__ __forceinline__ float sigf(float x) { return 1.0f / (1.0f + expf(-x)); }

// ---------------------------------------------------------------------------
// mma.sync LSTM step: z = [x|h] @ W (3-term split-bf16, K_eff = 3264), fused gates.
// Grid (32,16) = 512 CTAs, 4 CTAs/SM. 256 threads, 8 warps: wm=wid>>2 (2 m-slabs
// of 32), wn=wid&3 (4 n-slabs of 32). Warp tile 32x32. 2-stage pipeline.
// ---------------------------------------------------------------------------
__global__ __launch_bounds__(NTHR, 4)
void lstm_step_mma(int t, int T, int hsel, const float* __restrict__ bias)
{
    extern __shared__ char smem[];
    uint32_t sb = (uint32_t)__cvta_generic_to_shared(smem);
    const int tid  = threadIdx.x;
    const int wid  = tid >> 5;
    const int lane = tid & 31;
    const int wm   = wid >> 2;        // 0..1
    const int wn   = wid & 3;         // 0..3
    const int m0   = blockIdx.y * MT;
    const int n0   = blockIdx.x * NT;

    const __nv_bfloat16* xh; const __nv_bfloat16* xl; long xstr;
    if (t >= 0) { xh = g_Xhi + (long)t * I_; xl = g_Xlo + (long)t * I_; xstr = (long)T * I_; }
    else        { xh = g_ph;                 xl = g_pl;                 xstr = I_; }
    const __nv_bfloat16* hh = g_Ahh[hsel];
    const __nv_bfloat16* hl = g_Ahl[hsel];

    // --- stage loader: A 64x64 (8KB) + B 128x64 (16KB), 6 cp.async/thread ---
    auto load_stage = [&](int s, int buf) {
        int seg = s / STG_PER_SEG;
        int sis = s - seg * STG_PER_SEG;
        // segments: 0: Ahi*Whi   1: Alo*Whi   2: Ahi*Wlo
        const __nv_bfloat16* asrc; long astr;
        if (sis == 0) { asrc = (seg == 1) ? xl : xh;                      astr = xstr; }
        else          { asrc = ((seg == 1) ? hl : hh) + (sis - 1) * KC;   astr = U_;  }
        const __nv_bfloat16* bsrc = ((seg == 2) ? g_Wlo : g_Whi) + sis * KC;
        uint32_t ab = sb + S_A_OFF + (uint32_t)buf * STAGE_BYTES;
        uint32_t bb = ab + 8192;
#pragma unroll
        for (int i = 0; i < 2; i++) {               // A: 512 x 16B
            int idx = tid + i * NTHR;
            int r = idx >> 3, cb = (idx & 7) << 4;
            uint32_t off = (uint32_t)(r * 128 + cb); off ^= (off >> 3) & 0x70;
            const char* src = (const char*)(asrc + (long)(m0 + r) * astr) + cb;
            asm volatile("cp.async.cg.shared.global [%0], [%1], 16;" :: "r"(ab + off), "l"(src));
        }
#pragma unroll
        for (int i = 0; i < 4; i++) {               // B: 1024 x 16B
            int idx = tid + i * NTHR;
            int r = idx >> 3, cb = (idx & 7) << 4;
            uint32_t off = (uint32_t)(r * 128 + cb); off ^= (off >> 3) & 0x70;
            const char* src = (const char*)(bsrc + (long)(n0 + r) * KSEG) + cb;
            asm volatile("cp.async.cg.shared.global [%0], [%1], 16;" :: "r"(bb + off), "l"(src));
        }
        asm volatile("cp.async.commit_group;" ::: "memory");
    };

    float acc[2][4][4];
#pragma unroll
    for (int i = 0; i < 2; i++)
#pragma unroll
        for (int j = 0; j < 4; j++) {
            acc[i][j][0] = 0.f; acc[i][j][1] = 0.f;
            acc[i][j][2] = 0.f; acc[i][j][3] = 0.f;
        }

    uint32_t afr[2][4];     // 2 m16 tiles
    uint32_t bfr[4][2];     // 4 n8 tiles

    // per-thread constant address parts
    const uint32_t a_row_off = (uint32_t)((wm * 32 + (lane & 15)) * 128 + ((lane >> 4) << 4));
    const uint32_t b_row_off = (uint32_t)((wn * 32 + ((lane >> 4) << 3) + (lane & 7)) * 128
                                          + (((lane >> 3) & 1) << 4));

    load_stage(0, 0);

    for (int s = 0; s < NSTG; s++) {
        if (s + 1 < NSTG) load_stage(s + 1, (s + 1) & 1);
        if (s + 1 < NSTG) asm volatile("cp.async.wait_group 1;" ::: "memory");
        else              asm volatile("cp.async.wait_group 0;" ::: "memory");
        __syncthreads();                         // stage s visible

        uint32_t ab = sb + S_A_OFF + (uint32_t)(s & 1) * STAGE_BYTES;
        uint32_t bb = ab + 8192;
#pragma unroll
        for (int kk = 0; kk < 4; kk++) {
#pragma unroll
            for (int i = 0; i < 2; i++) {
                uint32_t off = a_row_off + (uint32_t)(i * 2048 + kk * 32);
                off ^= (off >> 3) & 0x70;
                asm volatile("ldmatrix.sync.aligned.m8n8.x4.shared.b16 {%0,%1,%2,%3}, [%4];"
                    : "=r"(afr[i][0]), "=r"(afr[i][1]), "=r"(afr[i][2]), "=r"(afr[i][3])
                    : "r"(ab + off));
            }
#pragma unroll
            for (int jj = 0; jj < 2; jj++) {
                uint32_t off = b_row_off + (uint32_t)(jj * 2048 + kk * 32);
                off ^= (off >> 3) & 0x70;
                uint32_t r0, r1, r2, r3;
                asm volatile("ldmatrix.sync.aligned.m8n8.x4.shared.b16 {%0,%1,%2,%3}, [%4];"
                    : "=r"(r0), "=r"(r1), "=r"(r2), "=r"(r3) : "r"(bb + off));
                bfr[jj * 2][0] = r0;     bfr[jj * 2][1] = r1;
                bfr[jj * 2 + 1][0] = r2; bfr[jj * 2 + 1][1] = r3;
            }
#pragma unroll
            for (int i = 0; i < 2; i++)
#pragma unroll
                for (int j = 0; j < 4; j++)
                    asm volatile(
                        "mma.sync.aligned.m16n8k16.row.col.f32.bf16.bf16.f32 "
                        "{%0,%1,%2,%3}, {%4,%5,%6,%7}, {%8,%9}, {%0,%1,%2,%3};"
                        : "+f"(acc[i][j][0]), "+f"(acc[i][j][1]),
                          "+f"(acc[i][j][2]), "+f"(acc[i][j][3])
                        : "r"(afr[i][0]), "r"(afr[i][1]),
                          "r"(afr[i][2]), "r"(afr[i][3]),
                          "r"(bfr[j][0]), "r"(bfr[j][1]));
        }
        __syncthreads();                         // compute done -> buf may be overwritten
    }

    // --- fused gate epilogue straight from accumulators ---
    // cols n = n0 + wn*32 + j*8 + lp*2 + {0,1}; n = 4u+g => lane pair (lp even|odd)
    // holds all 4 gates of unit u = n0/4 + wn*8 + j*2 + lp/2.
    {
        const int nsel = hsel ^ 1;
        const int lp = lane & 3;
        const bool ev = (lp & 1) == 0;
#pragma unroll
        for (int i = 0; i < 2; i++)
#pragma unroll
            for (int j = 0; j < 4; j++) {
                float t0 = __shfl_xor_sync(0xffffffffu, acc[i][j][0], 1);
                float t1 = __shfl_xor_sync(0xffffffffu, acc[i][j][1], 1);
                float t2 = __shfl_xor_sync(0xffffffffu, acc[i][j][2], 1);
                float t3 = __shfl_xor_sync(0xffffffffu, acc[i][j][3], 1);
                float zi, zf, zg, zo; int bm;
                if (ev) {   // even lane: own (g0,g1) row r; partner supplies (g2,g3) row r
                    zi = acc[i][j][0]; zf = acc[i][j][1]; zg = t0; zo = t1;
                    bm = m0 + wm * 32 + i * 16 + (lane >> 2);
                } else {    // odd lane: partner (g0,g1) row r+8; own (g2,g3) row r+8
                    zi = t2; zf = t3; zg = acc[i][j][2]; zo = acc[i][j][3];
                    bm = m0 + wm * 32 + i * 16 + (lane >> 2) + 8;
                }
                int u = (n0 >> 2) + wn * 8 + j * 2 + (lp >> 1);
                zi += bias[u];
                zf += bias[U_ + u];
                zg += bias[2 * U_ + u];
                zo += bias[3 * U_ + u];
                long off = (long)bm * U_ + u;
                float cn = sigf(zf) * g_c[off] + sigf(zi) * tanhf(zg);
                float hn = sigf(zo) * tanhf(cn);
                g_c[off] = cn;
                g_h[off] = hn;
                __nv_bfloat16 hhi = __float2bfloat16(hn);
                g_Ahh[nsel][off] = hhi;
                g_Ahl[nsel][off] = __float2bfloat16(hn - __bfloat162float(hhi));
            }
    }
}

// ---------------------------------------------------------------------------
// Dense head: p = h @ Wd + bd; write bf16 hi/lo feedback + scatter outputs.
// ---------------------------------------------------------------------------
__global__ void pred_kernel(const float* __restrict__ Wd, const float* __restrict__ bd,
                            float* __restrict__ out, const int* __restrict__ idx,
                            int n_out, int S, int s)
{
    __shared__ float hs[4][U_];
    const int tid = threadIdx.x;                 // 256
    const int b0 = blockIdx.x * 4;
    for (int i = tid; i < 4 * U_; i += 256) {
        int r = i >> 10, k = i & 1023;
        hs[r][k] = g_h[(long)(b0 + r) * U_ + k];
    }
    __syncthreads();
    const int br = tid >> 6, j = tid & 63;
    const int b = b0 + br;
    float acc = 0.f;
#pragma unroll 8
    for (int k = 0; k < U_; k++)
        acc += hs[br][k] * Wd[k * I_ + j];
    acc += bd[j];
    __nv_bfloat16 hi = __float2bfloat16(acc);
    g_ph[b * I_ + j] = hi;
    g_pl[b * I_ + j] = __float2bfloat16(acc - __bfloat162float(hi));
    for (int jj = 0; jj < n_out; jj++)
        if (idx[jj] == j)
            out[((long)b * S + s) * n_out + jj] = acc;
}

// ---------------------------------------------------------------------------
// One-time conversions (run per launch; deterministic)
// ---------------------------------------------------------------------------
__global__ void conv_w(const float* __restrict__ Wk, const float* __restrict__ Wr)
{
    long i = (long)blockIdx.x * blockDim.x + threadIdx.x;
    if (i >= 4096L * KSEG) return;
    int n = (int)(i / KSEG), k = (int)(i % KSEG);
    int u = n >> 2, g = n & 3;
    float v = (k < I_) ? Wk[(long)k * 4096 + g * U_ + u]
                       : Wr[(long)(k - I_) * 4096 + g * U_ + u];
    __nv_bfloat16 hi = __float2bfloat16(v);
    g_Whi[i] = hi;
    g_Wlo[i] = __float2bfloat16(v - __bfloat162float(hi));
}

__global__ void conv_x(const float* __restrict__ X, long n)
{
    long i = (long)blockIdx.x * blockDim.x + threadIdx.x;
    if (i >= n) return;
    float v = X[i];
    __nv_bfloat16 hi = __float2bfloat16(v);
    g_Xhi[i] = hi;
    g_Xlo[i] = __float2bfloat16(v - __bfloat162float(hi));
}

__global__ void init_state()
{
    int i = blockIdx.x * blockDim.x + threadIdx.x;
    if (i < B_ * U_) {
        g_c[i] = 0.f;
        g_Ahh[0][i] = __float2bfloat16(0.f);
        g_Ahl[0][i] = __float2bfloat16(0.f);
    }
}

// ---------------------------------------------------------------------------
extern "C" void kernel_launch(void* const* d_in, const int* in_sizes, int n_in,
                              void* d_out, int out_size)
{
    const float* inputs = (const float*)d_in[0];   // [B, T, I]
    const float* Wk     = (const float*)d_in[1];   // [I, 4U]
    const float* Wr     = (const float*)d_in[2];   // [U, 4U]
    const float* b      = (const float*)d_in[3];   // [4U]
    const float* Wd     = (const float*)d_in[4];   // [U, I]
    const float* bd     = (const float*)d_in[5];   // [I]
    const int*   idx    = (const int*)d_in[6];     // output_indices
    int n_out = in_sizes[6];
    int T     = in_sizes[0] / (B_ * I_);
    int S     = out_size / (B_ * n_out);
    float* out = (float*)d_out;

    cudaFuncSetAttribute(lstm_step_mma, cudaFuncAttributeMaxDynamicSharedMemorySize, S_TOTAL);

    conv_w<<<(int)((4096L * KSEG + 255) / 256), 256>>>(Wk, Wr);
    conv_x<<<(int)(((long)B_ * T * I_ + 255) / 256), 256>>>(inputs, (long)B_ * T * I_);
    init_state<<<(B_ * U_ + 255) / 256, 256>>>();

    dim3 grid(4 * U_ / NT, B_ / MT);   // (32, 16) = 512 CTAs

    int cur = 0;
    for (int t = 0; t < T; t++) {
        lstm_step_mma<<<grid, NTHR, S_TOTAL>>>(t, T, cur, b);
        cur ^= 1;
    }
    pred_kernel<<<B_ / 4, 256>>>(Wd, bd, out, idx, n_out, S, 0);
    for (int s = 1; s < S; s++) {
        lstm_step_mma<<<grid, NTHR, S_TOTAL>>>(-1, T, cur, b);
        cur ^= 1;
        pred_kernel<<<B_ / 4, 256>>>(Wd, bd, out, idx, n_out, S, s);
    }
}